// round 1
// baseline (speedup 1.0000x reference)
#include <cuda_runtime.h>
#include <cstdint>

// Instant-NGP fused forward: 16-level 2D hashgrid encode + MLP 32->64->64->3 (ReLU)
// One thread per point. Weights cached in shared (broadcast reads).
// Levels 0..5 dense (res = 16<<lvl, res^2 <= 2^19), levels 6..15 spatial-hashed.

constexpr int NLV = 16;
constexpr int TSZ = 1 << 19;           // 524288 entries per level
constexpr unsigned PRIME_Y = 2654435761u;

__global__ __launch_bounds__(128) void ngp_fused(
    const float* __restrict__ pos,      // [N,2]
    const float* __restrict__ table,    // [16, TSZ, 2]
    const float* __restrict__ gW1,      // [32,64]
    const float* __restrict__ gW2,      // [64,64]
    const float* __restrict__ gW3,      // [64,3]
    float* __restrict__ out,            // [N,3]
    int n)
{
    __shared__ float sW1[32 * 64];
    __shared__ float sW2[64 * 64];
    __shared__ float sW3[64 * 3];
    for (int i = threadIdx.x; i < 32 * 64; i += 128) sW1[i] = gW1[i];
    for (int i = threadIdx.x; i < 64 * 64; i += 128) sW2[i] = gW2[i];
    for (int i = threadIdx.x; i < 64 * 3;  i += 128) sW3[i] = gW3[i];
    __syncthreads();

    int idx = blockIdx.x * 128 + threadIdx.x;
    if (idx >= n) return;

    const float2 p = ((const float2*)pos)[idx];

    // ---- hash-grid encode -> feat[32] ----
    float feat[32];
#pragma unroll
    for (int lvl = 0; lvl < NLV; lvl++) {
        const int res = 16 << lvl;                 // ceil(scale)+1, scale integer
        const float scale = (float)(res - 1);      // BASE_RES*2^lvl - 1, exact fp32
        float px = p.x * scale + 0.5f;
        float py = p.y * scale + 0.5f;
        float fx = floorf(px), fy = floorf(py);
        float wx = px - fx,    wy = py - fy;
        unsigned cx = (unsigned)fx, cy = (unsigned)fy;

        unsigned i00, i10, i01, i11;
        if ((long long)res * res <= TSZ) {         // dense (compile-time per level)
            i00 = cx + cy * (unsigned)res;
            i10 = i00 + 1u;
            i01 = i00 + (unsigned)res;
            i11 = i01 + 1u;
        } else {                                   // tcnn spatial hash
            unsigned hy0 = cy * PRIME_Y;
            unsigned hy1 = (cy + 1u) * PRIME_Y;
            i00 = (cx        ^ hy0) & (unsigned)(TSZ - 1);
            i10 = ((cx + 1u) ^ hy0) & (unsigned)(TSZ - 1);
            i01 = (cx        ^ hy1) & (unsigned)(TSZ - 1);
            i11 = ((cx + 1u) ^ hy1) & (unsigned)(TSZ - 1);
        }

        const float2* tl = (const float2*)table + (size_t)lvl * TSZ;
        float2 v00 = __ldg(tl + i00);
        float2 v10 = __ldg(tl + i10);
        float2 v01 = __ldg(tl + i01);
        float2 v11 = __ldg(tl + i11);

        float w00 = (1.f - wx) * (1.f - wy);
        float w10 = wx * (1.f - wy);
        float w01 = (1.f - wx) * wy;
        float w11 = wx * wy;

        feat[lvl * 2 + 0] = w00 * v00.x + w10 * v10.x + w01 * v01.x + w11 * v11.x;
        feat[lvl * 2 + 1] = w00 * v00.y + w10 * v10.y + w01 * v01.y + w11 * v11.y;
    }

    // ---- layer 1: [32] @ [32,64] + ReLU ----
    float h1[64];
#pragma unroll
    for (int j = 0; j < 64; j++) h1[j] = 0.f;
#pragma unroll
    for (int i = 0; i < 32; i++) {
        float f = feat[i];
        const float4* w4 = (const float4*)(sW1 + i * 64);
#pragma unroll
        for (int j = 0; j < 16; j++) {
            float4 w = w4[j];
            h1[4 * j + 0] += f * w.x;
            h1[4 * j + 1] += f * w.y;
            h1[4 * j + 2] += f * w.z;
            h1[4 * j + 3] += f * w.w;
        }
    }
#pragma unroll
    for (int j = 0; j < 64; j++) h1[j] = fmaxf(h1[j], 0.f);

    // ---- layer 2: [64] @ [64,64] + ReLU ----
    float h2[64];
#pragma unroll
    for (int j = 0; j < 64; j++) h2[j] = 0.f;
#pragma unroll
    for (int i = 0; i < 64; i++) {
        float f = h1[i];
        const float4* w4 = (const float4*)(sW2 + i * 64);
#pragma unroll
        for (int j = 0; j < 16; j++) {
            float4 w = w4[j];
            h2[4 * j + 0] += f * w.x;
            h2[4 * j + 1] += f * w.y;
            h2[4 * j + 2] += f * w.z;
            h2[4 * j + 3] += f * w.w;
        }
    }
#pragma unroll
    for (int j = 0; j < 64; j++) h2[j] = fmaxf(h2[j], 0.f);

    // ---- layer 3: [64] @ [64,3] ----
    float o0 = 0.f, o1 = 0.f, o2 = 0.f;
#pragma unroll
    for (int i = 0; i < 64; i++) {
        float f = h2[i];
        o0 += f * sW3[i * 3 + 0];
        o1 += f * sW3[i * 3 + 1];
        o2 += f * sW3[i * 3 + 2];
    }

    out[idx * 3 + 0] = o0;
    out[idx * 3 + 1] = o1;
    out[idx * 3 + 2] = o2;
}

extern "C" void kernel_launch(void* const* d_in, const int* in_sizes, int n_in,
                              void* d_out, int out_size) {
    const float* pos   = (const float*)d_in[0];
    const float* table = (const float*)d_in[1];
    const float* W1    = (const float*)d_in[2];
    const float* W2    = (const float*)d_in[3];
    const float* W3    = (const float*)d_in[4];
    float* out = (float*)d_out;
    int n = in_sizes[0] / 2;
    int blocks = (n + 127) / 128;
    ngp_fused<<<blocks, 128>>>(pos, table, W1, W2, W3, out, n);
}

// round 2
// speedup vs baseline: 1.5389x; 1.5389x over previous
#include <cuda_runtime.h>
#include <cstdint>

// Instant-NGP fused forward: 16-level 2D hashgrid encode + MLP 32->64->64->3 (ReLU)
// R2: register-pressure-optimized. Layer1 folded into encode loop (feat[] never
// materialized); layer3 folded into layer2 chunk loop (h2[] never materialized).
// Peak live-set ~= h1[64] + temps -> launch_bounds(128,5) caps regs at 102,
// giving 20 warps/SM instead of 8.

constexpr int NLV = 16;
constexpr int TSZ = 1 << 19;           // 524288 entries per level
constexpr unsigned PRIME_Y = 2654435761u;

__global__ __launch_bounds__(128, 5) void ngp_fused(
    const float* __restrict__ pos,      // [N,2]
    const float* __restrict__ table,    // [16, TSZ, 2]
    const float* __restrict__ gW1,      // [32,64]
    const float* __restrict__ gW2,      // [64,64]
    const float* __restrict__ gW3,      // [64,3]
    float* __restrict__ out,            // [N,3]
    int n)
{
    __shared__ float sW1[32 * 64];
    __shared__ float sW2[64 * 64];
    __shared__ float sW3[64 * 3];
    for (int i = threadIdx.x; i < 32 * 64; i += 128) sW1[i] = gW1[i];
    for (int i = threadIdx.x; i < 64 * 64; i += 128) sW2[i] = gW2[i];
    for (int i = threadIdx.x; i < 64 * 3;  i += 128) sW3[i] = gW3[i];
    __syncthreads();

    int idx = blockIdx.x * 128 + threadIdx.x;
    if (idx >= n) return;

    const float2 p = ((const float2*)pos)[idx];

    // ---- hash-grid encode, layer-1 folded in: h1[j] = sum_lvl f*W1row ----
    float h1[64];
#pragma unroll
    for (int j = 0; j < 64; j++) h1[j] = 0.f;

#pragma unroll
    for (int lvl = 0; lvl < NLV; lvl++) {
        const int res = 16 << lvl;                 // ceil(scale)+1, scale integer
        const float scale = (float)(res - 1);      // BASE_RES*2^lvl - 1, exact fp32
        float px = p.x * scale + 0.5f;
        float py = p.y * scale + 0.5f;
        float fx = floorf(px), fy = floorf(py);
        float wx = px - fx,    wy = py - fy;
        unsigned cx = (unsigned)fx, cy = (unsigned)fy;

        unsigned i00, i10, i01, i11;
        if ((long long)res * res <= TSZ) {         // dense (compile-time per level)
            i00 = cx + cy * (unsigned)res;
            i10 = i00 + 1u;
            i01 = i00 + (unsigned)res;
            i11 = i01 + 1u;
        } else {                                   // tcnn spatial hash
            unsigned hy0 = cy * PRIME_Y;
            unsigned hy1 = (cy + 1u) * PRIME_Y;
            i00 = (cx        ^ hy0) & (unsigned)(TSZ - 1);
            i10 = ((cx + 1u) ^ hy0) & (unsigned)(TSZ - 1);
            i01 = (cx        ^ hy1) & (unsigned)(TSZ - 1);
            i11 = ((cx + 1u) ^ hy1) & (unsigned)(TSZ - 1);
        }

        const float2* tl = (const float2*)table + (size_t)lvl * TSZ;
        float2 v00 = __ldg(tl + i00);
        float2 v10 = __ldg(tl + i10);
        float2 v01 = __ldg(tl + i01);
        float2 v11 = __ldg(tl + i11);

        float w00 = (1.f - wx) * (1.f - wy);
        float w10 = wx * (1.f - wy);
        float w01 = (1.f - wx) * wy;
        float w11 = wx * wy;

        float f0 = w00 * v00.x + w10 * v10.x + w01 * v01.x + w11 * v11.x;
        float f1 = w00 * v00.y + w10 * v10.y + w01 * v01.y + w11 * v11.y;

        // fold into layer 1 immediately (feat never stored)
        const float4* wr0 = (const float4*)(sW1 + (2 * lvl + 0) * 64);
        const float4* wr1 = (const float4*)(sW1 + (2 * lvl + 1) * 64);
#pragma unroll
        for (int j = 0; j < 16; j++) {
            float4 a = wr0[j];
            float4 b = wr1[j];
            h1[4 * j + 0] += f0 * a.x + f1 * b.x;
            h1[4 * j + 1] += f0 * a.y + f1 * b.y;
            h1[4 * j + 2] += f0 * a.z + f1 * b.z;
            h1[4 * j + 3] += f0 * a.w + f1 * b.w;
        }
    }

#pragma unroll
    for (int j = 0; j < 64; j++) h1[j] = fmaxf(h1[j], 0.f);

    // ---- layer 2 (chunks of 8) with layer 3 folded in; h2 never stored ----
    float o0 = 0.f, o1 = 0.f, o2 = 0.f;
#pragma unroll
    for (int jc = 0; jc < 8; jc++) {
        float c[8];
#pragma unroll
        for (int k = 0; k < 8; k++) c[k] = 0.f;
#pragma unroll
        for (int i = 0; i < 64; i++) {
            float f = h1[i];
            const float4* w4 = (const float4*)(sW2 + i * 64 + jc * 8);
            float4 a = w4[0];
            float4 b = w4[1];
            c[0] += f * a.x; c[1] += f * a.y; c[2] += f * a.z; c[3] += f * a.w;
            c[4] += f * b.x; c[5] += f * b.y; c[6] += f * b.z; c[7] += f * b.w;
        }
#pragma unroll
        for (int k = 0; k < 8; k++) {
            float h = fmaxf(c[k], 0.f);
            int j = jc * 8 + k;
            o0 += h * sW3[j * 3 + 0];
            o1 += h * sW3[j * 3 + 1];
            o2 += h * sW3[j * 3 + 2];
        }
    }

    out[idx * 3 + 0] = o0;
    out[idx * 3 + 1] = o1;
    out[idx * 3 + 2] = o2;
}

extern "C" void kernel_launch(void* const* d_in, const int* in_sizes, int n_in,
                              void* d_out, int out_size) {
    const float* pos   = (const float*)d_in[0];
    const float* table = (const float*)d_in[1];
    const float* W1    = (const float*)d_in[2];
    const float* W2    = (const float*)d_in[3];
    const float* W3    = (const float*)d_in[4];
    float* out = (float*)d_out;
    int n = in_sizes[0] / 2;
    int blocks = (n + 127) / 128;
    ngp_fused<<<blocks, 128>>>(pos, table, W1, W2, W3, out, n);
}